// round 12
// baseline (speedup 1.0000x reference)
#include <cuda_runtime.h>
#include <cstdint>

// ============================================================================
// BLinear: out[t][o] = sum_i sign(x[t,i])*sign(W[o,i]) + b[o]
// sm_100 (no tcgen05). s8 +-1 encode -> mma.sync m16n8k32 s32 IMMA GEMM ->
// float + bias. Integer accumulation is exact (rel_err 0).
// R8 skeleton (per-thread cp.async + wait_group + __syncthreads, 64x32 warp
// tile) at 16 warps/CTA (TM=128, TN=256, TPB=512): 4 warps/SMSP resident to
// overlap the tensor + L1 pipes.
// ============================================================================

#define TPB 512
#define TM 128
#define TN 256
#define TKB 64                    // K bytes per stage
#define STAGES 5

#define A_BYTES (TM * TKB)        // 8192
#define B_BYTES (TN * TKB)        // 16384
#define STAGE_BYTES (A_BYTES + B_BYTES)     // 24576
#define SMEM_TOTAL (STAGES * STAGE_BYTES)   // 122880

// Scratch (allocation rules: __device__ globals)
__device__ __align__(256) int8_t g_Xa[8192u * 2048u];   // 16 MB packed x
__device__ __align__(256) int8_t g_Wb[2048u * 2048u];   //  4 MB packed W

__device__ __forceinline__ uint32_t smem_u32(const void* p) {
    uint32_t a;
    asm("{ .reg .u64 t; cvta.to.shared.u64 t, %1; cvt.u32.u64 %0, t; }"
        : "=r"(a) : "l"(p));
    return a;
}
__device__ __forceinline__ void cp16(uint32_t dst, const void* src) {
    asm volatile("cp.async.cg.shared.global [%0], [%1], 16;"
        :: "r"(dst), "l"(src) : "memory");
}
#define CP_COMMIT() asm volatile("cp.async.commit_group;" ::: "memory")
#define CP_WAIT(n)  asm volatile("cp.async.wait_group %0;" :: "n"(n) : "memory")

__device__ __forceinline__ void ldm_x4(uint32_t& r0, uint32_t& r1,
                                       uint32_t& r2, uint32_t& r3, uint32_t addr) {
    asm volatile("ldmatrix.sync.aligned.m8n8.x4.shared.b16 {%0,%1,%2,%3}, [%4];"
        : "=r"(r0), "=r"(r1), "=r"(r2), "=r"(r3) : "r"(addr));
}
__device__ __forceinline__ void imma(int* d, const uint32_t* a, const uint32_t* b) {
    asm volatile("mma.sync.aligned.m16n8k32.row.col.s32.s8.s8.s32 "
        "{%0,%1,%2,%3}, {%4,%5,%6,%7}, {%8,%9}, {%0,%1,%2,%3};"
        : "+r"(d[0]), "+r"(d[1]), "+r"(d[2]), "+r"(d[3])
        : "r"(a[0]), "r"(a[1]), "r"(a[2]), "r"(a[3]), "r"(b[0]), "r"(b[1]));
}

// 16B-chunk XOR swizzle within a 64B k-row: conflict-free for cp.async stores
// and for ldmatrix 8-row read phases. (Validated rounds 4/5/8/9.)
__device__ __forceinline__ uint32_t swz(int r, int c) {
    return (uint32_t)(r * TKB + ((c ^ ((r >> 1) & 3)) << 4));
}

// ---------------------------------------------------------------------------
// Fused pack: fp32 -> s8 sign (+1 -> 0x01, -1 -> 0xFF); 16 bytes out per iter.
// Blocks [0, PACK_XB) pack x; blocks [PACK_XB, PACK_XB+PACK_WB) pack W.
// (Identical to the validated round-8 kernel.)
// ---------------------------------------------------------------------------
#define PACK_XB 2048
#define PACK_WB 512
__global__ void __launch_bounds__(256)
pack_fused(const float* __restrict__ x, int8_t* __restrict__ xa,
           const float* __restrict__ W, int8_t* __restrict__ wb,
           int nx16, int nw16)
{
    const bool isX = blockIdx.x < PACK_XB;
    const float* src = isX ? x : W;
    int8_t* dst      = isX ? xa : wb;
    const int n16    = isX ? nx16 : nw16;
    const int nblk   = isX ? PACK_XB : PACK_WB;
    const int bid    = isX ? blockIdx.x : blockIdx.x - PACK_XB;

    int idx = bid * 256 + threadIdx.x;
    int stride = nblk * 256;
    const float4* s4 = (const float4*)src;
    uint4* d4 = (uint4*)dst;
    for (int i = idx; i < n16; i += stride) {
        uint32_t w[4];
#pragma unroll
        for (int k = 0; k < 4; k++) {
            float4 f = s4[(size_t)i * 4 + k];
            uint32_t sb = (__float_as_uint(f.x) >> 31)
                        | ((__float_as_uint(f.y) >> 31) << 8)
                        | ((__float_as_uint(f.z) >> 31) << 16)
                        | ((__float_as_uint(f.w) >> 31) << 24);
            w[k] = 0x01010101u ^ (sb * 0xFEu);   // per byte: 0x01 or 0xFF
        }
        d4[i] = make_uint4(w[0], w[1], w[2], w[3]);
    }
}

// ---------------------------------------------------------------------------
// IMMA GEMM: out[T,O] = A[T,K]s8 @ B[O,K]s8^T (as s32) + bias, fp32 out.
// Block 128x256, 16 warps of 64x32, 5-stage cp.async pipeline.
// ---------------------------------------------------------------------------
__global__ void __launch_bounds__(TPB, 1)
bgemm_imma(const int8_t* __restrict__ A, const int8_t* __restrict__ B,
           const float* __restrict__ bias, float* __restrict__ out,
           int T, int O, int Kb)
{
    extern __shared__ char smem[];
    const uint32_t sm = smem_u32(smem);
    const int tid  = threadIdx.x;
    const int wid  = tid >> 5;
    const int lane = tid & 31;
    const int m0 = blockIdx.y * TM;
    const int n0 = blockIdx.x * TN;
    const int KCH = Kb / TKB;

    const int warp_m = (wid & 1) * 64;    // 2 m-groups of 64
    const int warp_n = (wid >> 1) * 32;   // 8 n-groups of 32

    // per-lane ldmatrix source offsets (stage-relative), both ksteps
    const int mat = lane >> 3, rin = lane & 7;
    uint32_t relA[4][2], relB[2][2];
#pragma unroll
    for (int mf = 0; mf < 4; mf++) {
        int r = warp_m + mf * 16 + (mat & 1) * 8 + rin;
        int cpar = mat >> 1;
#pragma unroll
        for (int ks = 0; ks < 2; ks++)
            relA[mf][ks] = swz(r, 2 * ks + cpar);
    }
#pragma unroll
    for (int g = 0; g < 2; g++) {
        int r = warp_n + g * 16 + (mat >> 1) * 8 + rin;
        int cpar = mat & 1;
#pragma unroll
        for (int ks = 0; ks < 2; ks++)
            relB[g][ks] = (uint32_t)A_BYTES + swz(r, 2 * ks + cpar);
    }

    const int8_t* gA = A + (size_t)m0 * Kb;
    const int8_t* gB = B + (size_t)n0 * Kb;

    // cp.async task split: 1536 chunks; i<512 -> A (r=i>>2,c=i&3), else B
    const int i0 = tid;                    // + k*TPB, k=0..2
    auto load_stage = [&](int slot, int ch) {
        uint32_t sbase = sm + slot * STAGE_BYTES;
        size_t koff = (size_t)ch * TKB;
        for (int k = 0; k < 3; k++) {
            int i = i0 + k * TPB;
            if (i < 512) {
                int r = i >> 2, c = i & 3;
                cp16(sbase + swz(r, c), gA + (size_t)r * Kb + koff + c * 16);
            } else {
                int j = i - 512;
                int r = j >> 2, c = j & 3;
                cp16(sbase + A_BYTES + swz(r, c),
                     gB + (size_t)r * Kb + koff + c * 16);
            }
        }
    };

    int acc[4][4][4];
#pragma unroll
    for (int a = 0; a < 4; a++)
#pragma unroll
        for (int b = 0; b < 4; b++)
#pragma unroll
            for (int c = 0; c < 4; c++) acc[a][b][c] = 0;

    // prologue: fill stages 0..3
    for (int s = 0; s < STAGES - 1; s++) {
        load_stage(s, s);
        CP_COMMIT();
    }

    for (int it = 0; it < KCH; it++) {
        const int slot = it % STAGES;
        CP_WAIT(STAGES - 2);
        __syncthreads();

        const uint32_t sbase = sm + slot * STAGE_BYTES;
#pragma unroll
        for (int ks = 0; ks < 2; ks++) {
            uint32_t a[4][4], b[2][4];
#pragma unroll
            for (int mf = 0; mf < 4; mf++)
                ldm_x4(a[mf][0], a[mf][1], a[mf][2], a[mf][3],
                       sbase + relA[mf][ks]);
#pragma unroll
            for (int g = 0; g < 2; g++)
                ldm_x4(b[g][0], b[g][1], b[g][2], b[g][3],
                       sbase + relB[g][ks]);
#pragma unroll
            for (int mf = 0; mf < 4; mf++)
#pragma unroll
                for (int nf = 0; nf < 4; nf++)
                    imma(acc[mf][nf], a[mf], &b[nf >> 1][(nf & 1) * 2]);
        }

        const int ld = it + STAGES - 1;
        if (ld < KCH) load_stage(ld % STAGES, ld);
        CP_COMMIT();
    }

    // epilogue: s32 -> fp32 + bias, float2 stores (coalesced per quad)
    const int rbase = m0 + warp_m + (lane >> 2);
    const int cbase = n0 + warp_n + (lane & 3) * 2;
#pragma unroll
    for (int nf = 0; nf < 4; nf++) {
        const int col = cbase + nf * 8;
        const float2 bv = *(const float2*)&bias[col];
#pragma unroll
        for (int mf = 0; mf < 4; mf++) {
            const int r0 = rbase + mf * 16;
            float2 v0, v1;
            v0.x = (float)acc[mf][nf][0] + bv.x;
            v0.y = (float)acc[mf][nf][1] + bv.y;
            v1.x = (float)acc[mf][nf][2] + bv.x;
            v1.y = (float)acc[mf][nf][3] + bv.y;
            *(float2*)&out[(size_t)r0 * O + col] = v0;
            *(float2*)&out[(size_t)(r0 + 8) * O + col] = v1;
        }
    }
}

// ---------------------------------------------------------------------------
// Launch
// ---------------------------------------------------------------------------
extern "C" void kernel_launch(void* const* d_in, const int* in_sizes, int n_in,
                              void* d_out, int out_size)
{
    const float* x = (const float*)d_in[0];
    const float* W = (const float*)d_in[1];
    const float* b = (const float*)d_in[2];
    float* out = (float*)d_out;

    const int O = in_sizes[2];            // out_features
    const int I = in_sizes[1] / O;        // in_features (K)
    const int T = in_sizes[0] / I;        // batch rows

    int8_t *Xa, *Wb;
    cudaGetSymbolAddress((void**)&Xa, g_Xa);
    cudaGetSymbolAddress((void**)&Wb, g_Wb);

    cudaFuncSetAttribute(bgemm_imma,
                         cudaFuncAttributeMaxDynamicSharedMemorySize, SMEM_TOTAL);

    pack_fused<<<PACK_XB + PACK_WB, 256>>>(x, Xa, W, Wb,
                                           (T * I) / 16, (O * I) / 16);

    dim3 grid(O / TN, T / TM);
    bgemm_imma<<<grid, TPB, SMEM_TOTAL>>>(Xa, Wb, b, out, T, O, I);
}

// round 14
// speedup vs baseline: 1.2072x; 1.2072x over previous
#include <cuda_runtime.h>
#include <cstdint>

// ============================================================================
// BLinear: out[t][o] = sum_i sign(x[t,i])*sign(W[o,i]) + b[o]
// sm_100 (no tcgen05). s8 +-1 encode -> mma.sync m16n8k32 s32 IMMA GEMM ->
// float + bias. Integer accumulation is exact (rel_err 0).
// Resubmit of round-13 (prior run hit an infra flake; R11->R12 precedent):
// R8 structure (128x128, 8 warps of 64x32, 2 CTAs/SM, per-thread cp.async +
// wait_group + __syncthreads) with 128B K-chunks (16 barriers instead of 32)
// and prefetch issued before the MMA burst.
// ============================================================================

#define TPB 256
#define TM 128
#define TN 128
#define TKB 128                   // K bytes per stage chunk
#define STAGES 3

#define A_BYTES (TM * TKB)        // 16384
#define STAGE_BYTES (2 * A_BYTES) // 32768 (A then B)
#define SMEM_TOTAL (STAGES * STAGE_BYTES)   // 98304

// Scratch (allocation rules: __device__ globals)
__device__ __align__(256) int8_t g_Xa[8192u * 2048u];   // 16 MB packed x
__device__ __align__(256) int8_t g_Wb[2048u * 2048u];   //  4 MB packed W

__device__ __forceinline__ uint32_t smem_u32(const void* p) {
    uint32_t a;
    asm("{ .reg .u64 t; cvta.to.shared.u64 t, %1; cvt.u32.u64 %0, t; }"
        : "=r"(a) : "l"(p));
    return a;
}
__device__ __forceinline__ void cp16(uint32_t dst, const void* src) {
    asm volatile("cp.async.cg.shared.global [%0], [%1], 16;"
        :: "r"(dst), "l"(src) : "memory");
}
#define CP_COMMIT() asm volatile("cp.async.commit_group;" ::: "memory")
#define CP_WAIT(n)  asm volatile("cp.async.wait_group %0;" :: "n"(n) : "memory")

__device__ __forceinline__ void ldm_x4(uint32_t& r0, uint32_t& r1,
                                       uint32_t& r2, uint32_t& r3, uint32_t addr) {
    asm volatile("ldmatrix.sync.aligned.m8n8.x4.shared.b16 {%0,%1,%2,%3}, [%4];"
        : "=r"(r0), "=r"(r1), "=r"(r2), "=r"(r3) : "r"(addr));
}
__device__ __forceinline__ void imma(int* d, const uint32_t* a, const uint32_t* b) {
    asm volatile("mma.sync.aligned.m16n8k32.row.col.s32.s8.s8.s32 "
        "{%0,%1,%2,%3}, {%4,%5,%6,%7}, {%8,%9}, {%0,%1,%2,%3};"
        : "+r"(d[0]), "+r"(d[1]), "+r"(d[2]), "+r"(d[3])
        : "r"(a[0]), "r"(a[1]), "r"(a[2]), "r"(a[3]), "r"(b[0]), "r"(b[1]));
}

// 16B-chunk XOR swizzle within a 128B k-row: chunk col c (0..7), row r.
// Stores: each warp phase covers a full 128B row -> all 32 banks, no conflict.
// ldmatrix: rows r..r+7 at logical chunk c map to 8 distinct chunk slots
// (c ^ (r&7) is a bijection over r&7) -> 8 distinct bank groups, no conflict.
__device__ __forceinline__ uint32_t swz128(int r, int c) {
    return (uint32_t)(r * TKB + (((c ^ (r & 7)) & 7) << 4));
}

// ---------------------------------------------------------------------------
// Fused pack: fp32 -> s8 sign (+1 -> 0x01, -1 -> 0xFF); 16 bytes out per iter.
// Plain linear [row][K] layout (identical to validated round-8 kernel).
// Blocks [0, PACK_XB) pack x; blocks [PACK_XB, PACK_XB+PACK_WB) pack W.
// ---------------------------------------------------------------------------
#define PACK_XB 2048
#define PACK_WB 512
__global__ void __launch_bounds__(256)
pack_fused(const float* __restrict__ x, int8_t* __restrict__ xa,
           const float* __restrict__ W, int8_t* __restrict__ wb,
           int nx16, int nw16)
{
    const bool isX = blockIdx.x < PACK_XB;
    const float* src = isX ? x : W;
    int8_t* dst      = isX ? xa : wb;
    const int n16    = isX ? nx16 : nw16;
    const int nblk   = isX ? PACK_XB : PACK_WB;
    const int bid    = isX ? blockIdx.x : blockIdx.x - PACK_XB;

    int idx = bid * 256 + threadIdx.x;
    int stride = nblk * 256;
    const float4* s4 = (const float4*)src;
    uint4* d4 = (uint4*)dst;
    for (int i = idx; i < n16; i += stride) {
        uint32_t w[4];
#pragma unroll
        for (int q = 0; q < 4; q++) {
            float4 f = s4[(size_t)i * 4 + q];
            uint32_t sb = (__float_as_uint(f.x) >> 31)
                        | ((__float_as_uint(f.y) >> 31) << 8)
                        | ((__float_as_uint(f.z) >> 31) << 16)
                        | ((__float_as_uint(f.w) >> 31) << 24);
            w[q] = 0x01010101u ^ (sb * 0xFEu);   // per byte: 0x01 or 0xFF
        }
        d4[i] = make_uint4(w[0], w[1], w[2], w[3]);
    }
}

// ---------------------------------------------------------------------------
// IMMA GEMM: out[T,O] = A[T,K]s8 @ B[O,K]s8^T (as s32) + bias, fp32 out.
// Block 128x128, 8 warps of 64x32, 3-stage pipeline of 128B K-chunks.
// ---------------------------------------------------------------------------
__global__ void __launch_bounds__(TPB, 2)
bgemm_imma(const int8_t* __restrict__ A, const int8_t* __restrict__ B,
           const float* __restrict__ bias, float* __restrict__ out,
           int T, int O, int Kb)
{
    extern __shared__ char smem[];
    const uint32_t sm = smem_u32(smem);
    const int tid  = threadIdx.x;
    const int wid  = tid >> 5;
    const int lane = tid & 31;
    const int m0 = blockIdx.y * TM;
    const int n0 = blockIdx.x * TN;
    const int KCH = Kb / TKB;          // 16

    const int warp_m = (wid & 1) * 64;    // 2 m-groups
    const int warp_n = (wid >> 1) * 32;   // 4 n-groups

    // per-lane ldmatrix row bases; swizzled chunk col computed per kstep
    const int mat = lane >> 3, rin = lane & 7;
    int rbA[4], rxA[4], rbB[2], rxB[2];
#pragma unroll
    for (int mf = 0; mf < 4; mf++) {
        int r = warp_m + mf * 16 + (mat & 1) * 8 + rin;
        rbA[mf] = r * TKB;  rxA[mf] = r & 7;
    }
#pragma unroll
    for (int g = 0; g < 2; g++) {
        int r = warp_n + g * 16 + (mat >> 1) * 8 + rin;
        rbB[g] = A_BYTES + r * TKB;  rxB[g] = r & 7;
    }
    const int cparA = mat >> 1, cparB = mat & 1;

    const int8_t* gA = A + (size_t)m0 * Kb;
    const int8_t* gB = B + (size_t)n0 * Kb;

    // cp.async task split: 2048 chunks; i<1024 -> A (r=i>>3,c=i&7), else B
    const int i0 = tid;                    // + k*TPB, k=0..7
    auto load_stage = [&](int slot, int ch) {
        uint32_t sbase = sm + slot * STAGE_BYTES;
        size_t koff = (size_t)ch * TKB;
        for (int k = 0; k < 8; k++) {
            int i = i0 + k * TPB;
            if (i < 1024) {
                int r = i >> 3, c = i & 7;
                cp16(sbase + swz128(r, c), gA + (size_t)r * Kb + koff + c * 16);
            } else {
                int j = i - 1024;
                int r = j >> 3, c = j & 7;
                cp16(sbase + A_BYTES + swz128(r, c),
                     gB + (size_t)r * Kb + koff + c * 16);
            }
        }
    };

    int acc[4][4][4];
#pragma unroll
    for (int a = 0; a < 4; a++)
#pragma unroll
        for (int b = 0; b < 4; b++)
#pragma unroll
            for (int c = 0; c < 4; c++) acc[a][b][c] = 0;

    // prologue: fill stages 0..1 with chunks 0..1
    for (int s = 0; s < STAGES - 1; s++) {
        load_stage(s, s);
        CP_COMMIT();
    }

    for (int it = 0; it < KCH; it++) {
        const int slot = it % STAGES;
        CP_WAIT(STAGES - 2);
        __syncthreads();

        // prefetch next chunk BEFORE the MMA burst. It targets slot
        // (it+2)%3 == (it-1)%3 (chunk it-1, fully consumed: every thread
        // passed this iteration's __syncthreads only after finishing the
        // previous iteration's MMA burst).
        const int ld = it + STAGES - 1;
        if (ld < KCH) load_stage(ld % STAGES, ld);
        CP_COMMIT();

        const uint32_t sbase = sm + slot * STAGE_BYTES;
#pragma unroll
        for (int ks = 0; ks < 4; ks++) {       // four 32B k-steps per chunk
            uint32_t a[4][4], b[2][4];
#pragma unroll
            for (int mf = 0; mf < 4; mf++) {
                int cs = ((2 * ks + cparA) ^ rxA[mf]) & 7;
                ldm_x4(a[mf][0], a[mf][1], a[mf][2], a[mf][3],
                       sbase + rbA[mf] + (cs << 4));
            }
#pragma unroll
            for (int g = 0; g < 2; g++) {
                int cs = ((2 * ks + cparB) ^ rxB[g]) & 7;
                ldm_x4(b[g][0], b[g][1], b[g][2], b[g][3],
                       sbase + rbB[g] + (cs << 4));
            }
#pragma unroll
            for (int mf = 0; mf < 4; mf++)
#pragma unroll
                for (int nf = 0; nf < 4; nf++)
                    imma(acc[mf][nf], a[mf], &b[nf >> 1][(nf & 1) * 2]);
        }
    }

    // epilogue: s32 -> fp32 + bias, float2 stores (coalesced per quad)
    const int rbase = m0 + warp_m + (lane >> 2);
    const int cbase = n0 + warp_n + (lane & 3) * 2;
#pragma unroll
    for (int nf = 0; nf < 4; nf++) {
        const int col = cbase + nf * 8;
        const float2 bv = *(const float2*)&bias[col];
#pragma unroll
        for (int mf = 0; mf < 4; mf++) {
            const int r0 = rbase + mf * 16;
            float2 v0, v1;
            v0.x = (float)acc[mf][nf][0] + bv.x;
            v0.y = (float)acc[mf][nf][1] + bv.y;
            v1.x = (float)acc[mf][nf][2] + bv.x;
            v1.y = (float)acc[mf][nf][3] + bv.y;
            *(float2*)&out[(size_t)r0 * O + col] = v0;
            *(float2*)&out[(size_t)(r0 + 8) * O + col] = v1;
        }
    }
}

// ---------------------------------------------------------------------------
// Launch
// ---------------------------------------------------------------------------
extern "C" void kernel_launch(void* const* d_in, const int* in_sizes, int n_in,
                              void* d_out, int out_size)
{
    const float* x = (const float*)d_in[0];
    const float* W = (const float*)d_in[1];
    const float* b = (const float*)d_in[2];
    float* out = (float*)d_out;

    const int O = in_sizes[2];            // out_features
    const int I = in_sizes[1] / O;        // in_features (K)
    const int T = in_sizes[0] / I;        // batch rows

    int8_t *Xa, *Wb;
    cudaGetSymbolAddress((void**)&Xa, g_Xa);
    cudaGetSymbolAddress((void**)&Wb, g_Wb);

    cudaFuncSetAttribute(bgemm_imma,
                         cudaFuncAttributeMaxDynamicSharedMemorySize, SMEM_TOTAL);

    pack_fused<<<PACK_XB + PACK_WB, 256>>>(x, Xa, W, Wb,
                                           (T * I) / 16, (O * I) / 16);

    dim3 grid(O / TN, T / TM);
    bgemm_imma<<<grid, TPB, SMEM_TOTAL>>>(Xa, Wb, b, out, T, O, I);
}

// round 17
// speedup vs baseline: 1.2124x; 1.0043x over previous
#include <cuda_runtime.h>
#include <cstdint>

// ============================================================================
// BLinear: out[t][o] = sum_i sign(x[t,i])*sign(W[o,i]) + b[o]
// sm_100 (no tcgen05). s8 +-1 encode -> mma.sync m16n8k32 s32 IMMA GEMM ->
// float + bias. Integer accumulation is exact (rel_err 0).
// Third submission of the 4-domain design (two prior runs hit infra flakes;
// R11->R12 and R13->R14 resubmit precedents both passed).
// 4 CTAs/SM x 128 threads: 4 independent barrier domains per SM, 16 warps/SM
// aggregate. Tile 64x128, warp tile 32x64 (ldm:imma = 2.67). Validated
// R4/R8/R14 cp.async + wait_group + __syncthreads machinery throughout.
// ============================================================================

#define TPB 128
#define TM 64
#define TN 128
#define TKB 64                    // K bytes per stage chunk
#define STAGES 4

#define A_BYTES (TM * TKB)        // 4096
#define B_BYTES (TN * TKB)        // 8192
#define STAGE_BYTES (A_BYTES + B_BYTES)     // 12288
#define SMEM_TOTAL (STAGES * STAGE_BYTES)   // 49152

// Scratch (allocation rules: __device__ globals)
__device__ __align__(256) int8_t g_packA[8192u * 2048u];   // 16 MB packed x
__device__ __align__(256) int8_t g_packB[2048u * 2048u];   //  4 MB packed W

__device__ __forceinline__ uint32_t smem_addr32(const void* p) {
    uint32_t a;
    asm("{ .reg .u64 t; cvta.to.shared.u64 t, %1; cvt.u32.u64 %0, t; }"
        : "=r"(a) : "l"(p));
    return a;
}
__device__ __forceinline__ void cpa16(uint32_t dst, const void* src) {
    asm volatile("cp.async.cg.shared.global [%0], [%1], 16;"
        :: "r"(dst), "l"(src) : "memory");
}
#define CPA_COMMIT() asm volatile("cp.async.commit_group;" ::: "memory")
#define CPA_WAIT(n)  asm volatile("cp.async.wait_group %0;" :: "n"(n) : "memory")

__device__ __forceinline__ void ldsm4(uint32_t& r0, uint32_t& r1,
                                      uint32_t& r2, uint32_t& r3, uint32_t addr) {
    asm volatile("ldmatrix.sync.aligned.m8n8.x4.shared.b16 {%0,%1,%2,%3}, [%4];"
        : "=r"(r0), "=r"(r1), "=r"(r2), "=r"(r3) : "r"(addr));
}
__device__ __forceinline__ void mma_s8(int* d, const uint32_t* a, const uint32_t* b) {
    asm volatile("mma.sync.aligned.m16n8k32.row.col.s32.s8.s8.s32 "
        "{%0,%1,%2,%3}, {%4,%5,%6,%7}, {%8,%9}, {%0,%1,%2,%3};"
        : "+r"(d[0]), "+r"(d[1]), "+r"(d[2]), "+r"(d[3])
        : "r"(a[0]), "r"(a[1]), "r"(a[2]), "r"(a[3]), "r"(b[0]), "r"(b[1]));
}

// 16B-chunk XOR swizzle within a 64B k-row: conflict-free for cp.async stores
// and for ldmatrix 8-row read phases. (Validated rounds 4/5/8/14.)
__device__ __forceinline__ uint32_t swiz(int r, int c) {
    return (uint32_t)(r * TKB + ((c ^ ((r >> 1) & 3)) << 4));
}

// ---------------------------------------------------------------------------
// Fused pack: fp32 -> s8 sign (+1 -> 0x01, -1 -> 0xFF); 16 bytes out per iter.
// Plain linear [row][K] layout. (Identical to validated round-8/14 kernel.)
// Blocks [0, PK_XB) pack x; blocks [PK_XB, PK_XB+PK_WB) pack W.
// ---------------------------------------------------------------------------
#define PK_XB 2048
#define PK_WB 512
__global__ void __launch_bounds__(256)
sign_pack(const float* __restrict__ x, int8_t* __restrict__ xa,
          const float* __restrict__ W, int8_t* __restrict__ wb,
          int nx16, int nw16)
{
    const bool isX = blockIdx.x < PK_XB;
    const float* src = isX ? x : W;
    int8_t* dst      = isX ? xa : wb;
    const int n16    = isX ? nx16 : nw16;
    const int nblk   = isX ? PK_XB : PK_WB;
    const int bid    = isX ? blockIdx.x : blockIdx.x - PK_XB;

    int idx = bid * 256 + threadIdx.x;
    int stride = nblk * 256;
    const float4* s4 = (const float4*)src;
    uint4* d4 = (uint4*)dst;
    for (int i = idx; i < n16; i += stride) {
        uint32_t w[4];
#pragma unroll
        for (int q = 0; q < 4; q++) {
            float4 f = s4[(size_t)i * 4 + q];
            uint32_t sb = (__float_as_uint(f.x) >> 31)
                        | ((__float_as_uint(f.y) >> 31) << 8)
                        | ((__float_as_uint(f.z) >> 31) << 16)
                        | ((__float_as_uint(f.w) >> 31) << 24);
            w[q] = 0x01010101u ^ (sb * 0xFEu);   // per byte: 0x01 or 0xFF
        }
        d4[i] = make_uint4(w[0], w[1], w[2], w[3]);
    }
}

// ---------------------------------------------------------------------------
// IMMA GEMM: out[T,O] = A[T,K]s8 @ B[O,K]s8^T (as s32) + bias, fp32 out.
// Block 64x128, 4 warps of 32x64, 4-stage cp.async pipeline, 4 CTAs/SM.
// ---------------------------------------------------------------------------
__global__ void __launch_bounds__(TPB, 4)
gemm_s8_q(const int8_t* __restrict__ A, const int8_t* __restrict__ B,
          const float* __restrict__ bias, float* __restrict__ out,
          int T, int O, int Kb)
{
    extern __shared__ char smem[];
    const uint32_t sm = smem_addr32(smem);
    const int tid  = threadIdx.x;
    const int wid  = tid >> 5;
    const int lane = tid & 31;
    const int m0 = blockIdx.y * TM;
    const int n0 = blockIdx.x * TN;
    const int KCH = Kb / TKB;          // 32

    const int warp_m = (wid & 1) * 32;    // 2 m-groups of 32
    const int warp_n = (wid >> 1) * 64;   // 2 n-groups of 64

    // per-lane ldmatrix source offsets (stage-relative), both 32B ksteps
    const int mat = lane >> 3, rin = lane & 7;
    uint32_t relA[2][2], relB[4][2];
#pragma unroll
    for (int mf = 0; mf < 2; mf++) {
        int r = warp_m + mf * 16 + (mat & 1) * 8 + rin;
        int cpar = mat >> 1;
#pragma unroll
        for (int ks = 0; ks < 2; ks++)
            relA[mf][ks] = swiz(r, 2 * ks + cpar);
    }
#pragma unroll
    for (int g = 0; g < 4; g++) {
        int r = warp_n + g * 16 + (mat >> 1) * 8 + rin;
        int cpar = mat & 1;
#pragma unroll
        for (int ks = 0; ks < 2; ks++)
            relB[g][ks] = (uint32_t)A_BYTES + swiz(r, 2 * ks + cpar);
    }

    const int8_t* gA = A + (size_t)m0 * Kb;
    const int8_t* gB = B + (size_t)n0 * Kb;

    // cp.async task split: 768 chunks; i<256 -> A (r=i>>2,c=i&3), else B
    const int i0 = tid;                    // + k*TPB, k=0..5
    auto load_stage = [&](int slot, int ch) {
        uint32_t sbase = sm + slot * STAGE_BYTES;
        size_t koff = (size_t)ch * TKB;
        for (int k = 0; k < 6; k++) {
            int i = i0 + k * TPB;
            if (i < 256) {
                int r = i >> 2, c = i & 3;
                cpa16(sbase + swiz(r, c), gA + (size_t)r * Kb + koff + c * 16);
            } else {
                int j = i - 256;
                int r = j >> 2, c = j & 3;
                cpa16(sbase + A_BYTES + swiz(r, c),
                      gB + (size_t)r * Kb + koff + c * 16);
            }
        }
    };

    int acc[2][8][4];
#pragma unroll
    for (int a = 0; a < 2; a++)
#pragma unroll
        for (int b = 0; b < 8; b++)
#pragma unroll
            for (int c = 0; c < 4; c++) acc[a][b][c] = 0;

    // prologue: fill stages 0..2 with chunks 0..2
    for (int s = 0; s < STAGES - 1; s++) {
        load_stage(s, s);
        CPA_COMMIT();
    }

    for (int it = 0; it < KCH; it++) {
        const int slot = it % STAGES;
        CPA_WAIT(STAGES - 2);
        __syncthreads();

        // prefetch chunk it+3 into slot (it+3)%4 == (it-1)%4: chunk it-1 is
        // fully consumed (every thread passed this sync only after finishing
        // the previous iteration's MMA burst).
        const int ld = it + STAGES - 1;
        if (ld < KCH) load_stage(ld % STAGES, ld);
        CPA_COMMIT();

        const uint32_t sbase = sm + slot * STAGE_BYTES;
#pragma unroll
        for (int ks = 0; ks < 2; ks++) {
            uint32_t a[2][4], b[4][4];
#pragma unroll
            for (int mf = 0; mf < 2; mf++)
                ldsm4(a[mf][0], a[mf][1], a[mf][2], a[mf][3],
                      sbase + relA[mf][ks]);
#pragma unroll
            for (int g = 0; g < 4; g++)
                ldsm4(b[g][0], b[g][1], b[g][2], b[g][3],
                      sbase + relB[g][ks]);
#pragma unroll
            for (int mf = 0; mf < 2; mf++)
#pragma unroll
                for (int nf = 0; nf < 8; nf++)
                    mma_s8(acc[mf][nf], a[mf], &b[nf >> 1][(nf & 1) * 2]);
        }
    }

    // epilogue: s32 -> fp32 + bias, float2 stores (coalesced per quad)
    const int rbase = m0 + warp_m + (lane >> 2);
    const int cbase = n0 + warp_n + (lane & 3) * 2;
#pragma unroll
    for (int nf = 0; nf < 8; nf++) {
        const int col = cbase + nf * 8;
        const float2 bv = *(const float2*)&bias[col];
#pragma unroll
        for (int mf = 0; mf < 2; mf++) {
            const int r0 = rbase + mf * 16;
            float2 v0, v1;
            v0.x = (float)acc[mf][nf][0] + bv.x;
            v0.y = (float)acc[mf][nf][1] + bv.y;
            v1.x = (float)acc[mf][nf][2] + bv.x;
            v1.y = (float)acc[mf][nf][3] + bv.y;
            *(float2*)&out[(size_t)r0 * O + col] = v0;
            *(float2*)&out[(size_t)(r0 + 8) * O + col] = v1;
        }
    }
}

// ---------------------------------------------------------------------------
// Launch
// ---------------------------------------------------------------------------
extern "C" void kernel_launch(void* const* d_in, const int* in_sizes, int n_in,
                              void* d_out, int out_size)
{
    const float* x = (const float*)d_in[0];
    const float* W = (const float*)d_in[1];
    const float* b = (const float*)d_in[2];
    float* out = (float*)d_out;

    const int O = in_sizes[2];            // out_features
    const int I = in_sizes[1] / O;        // in_features (K)
    const int T = in_sizes[0] / I;        // batch rows

    int8_t *Xa, *Wb;
    cudaGetSymbolAddress((void**)&Xa, g_packA);
    cudaGetSymbolAddress((void**)&Wb, g_packB);

    cudaFuncSetAttribute(gemm_s8_q,
                         cudaFuncAttributeMaxDynamicSharedMemorySize, SMEM_TOTAL);

    sign_pack<<<PK_XB + PK_WB, 256>>>(x, Xa, W, Wb,
                                      (T * I) / 16, (O * I) / 16);

    dim3 grid(O / TN, T / TM);
    gemm_s8_q<<<grid, TPB, SMEM_TOTAL>>>(Xa, Wb, b, out, T, O, I);
}